// round 14
// baseline (speedup 1.0000x reference)
#include <cuda_runtime.h>
#include <cuda_fp16.h>
#include <cstdint>

// GRU decoder, H=4096, T=2048. Persistent single kernel + software grid barrier.
// R2: fp16 weight scratch -> L2-resident.   R6: batched loads + fast gates.
// R9: 9 warps' weights pinned in SMEM -> DRAM ~0%.
// R10: fp16 h in smem.  R12: Stage B on pinned warps.
// R13: flat HFMA2 group-flushed dots + fp16 h global buffer.       [14.96 ms]
// R14: warp load balancing. Pinned warps (LDS-only, finish early) now also
//      compute group g=3 (4/16 iterations) of TWO streaming rows each
//      (partials via smem + one mid-block sync). Stage B moves to streaming
//      warps 9..11 (which now only run 12 Stage-A iterations). Max per-warp
//      LDG exposure drops ~25% -> barrier stragglers removed.

#define HDIM 4096
#define IN_DIM 400
#define OROWS 401
#define NOUT 400
#define WARPS_PER_BLOCK 28
#define NTHREADS (WARPS_PER_BLOCK * 32)
#define PINNED_WARPS 9
#define N_STREAM (WARPS_PER_BLOCK - PINNED_WARPS)   // 19

#define SMEM_H_BYTES (HDIM * 2)                                  // 8192 (fp16 h)
#define PIN_HALVES (PINNED_WARPS * 3 * HDIM)                     // 110592 halves
#define SMEM_PART_OFF (SMEM_H_BYTES + PIN_HALVES * 2)            // 229376
#define SMEM_TOTAL (SMEM_PART_OFF + N_STREAM * 3 * 4)            // +228 B

__device__ __half g_whh_h[(size_t)3 * HDIM * HDIM];   // 100.7 MB fp16 W_hh
__device__ __half g_wout_h[(size_t)OROWS * HDIM];     // 3.3 MB fp16 W_out
__device__ float  g_h[2][HDIM];                       // fp32 hidden (recurrence)
__device__ __half g_h16[2][HDIM];                     // fp16 hidden (dot inputs)
__device__ float  g_gx[3 * HDIM];                     // W_ih @ relu(x) + b_ih
__device__ unsigned g_cnt;
__device__ unsigned g_gen;

__device__ __forceinline__ float warp_sum(float v) {
#pragma unroll
    for (int o = 16; o; o >>= 1) v += __shfl_xor_sync(0xffffffffu, v, o);
    return v;
}

// Sense-reversing grid barrier; all blocks co-resident (grid == #SMs, 1 blk/SM).
__device__ __forceinline__ void grid_sync() {
    __syncthreads();
    if (threadIdx.x == 0) {
        __threadfence();
        unsigned gen = *(volatile unsigned*)&g_gen;
        unsigned nblk = gridDim.x;
        if (atomicAdd(&g_cnt, 1u) == nblk - 1u) {
            atomicExch(&g_cnt, 0u);
            __threadfence();
            atomicAdd(&g_gen, 1u);
        } else {
            while (*(volatile unsigned*)&g_gen == gen) { __nanosleep(32); }
        }
        __threadfence();
    }
    __syncthreads();
}

__device__ __forceinline__ float fast_sigmoid(float x) {
    float e;
    asm("ex2.approx.f32 %0, %1;" : "=f"(e) : "f"(-1.4426950408889634f * x));
    float r;
    asm("rcp.approx.f32 %0, %1;" : "=f"(r) : "f"(1.0f + e));
    return r;
}
__device__ __forceinline__ float fast_tanh(float x) {
    float r;
    asm("tanh.approx.f32 %0, %1;" : "=f"(r) : "f"(x));
    return r;
}

// fp32-h variant for the final Stage B (h from global, fp32)
__device__ __forceinline__ float dot8f(uint4 u, float2 h0, float2 h1,
                                       float2 h2, float2 h3) {
    float2 p; float s0 = 0.f, s1 = 0.f;
    p = __half22float2(*(const __half2*)&u.x); s0 += p.x * h0.x; s1 += p.y * h0.y;
    p = __half22float2(*(const __half2*)&u.y); s0 += p.x * h1.x; s1 += p.y * h1.y;
    p = __half22float2(*(const __half2*)&u.z); s0 += p.x * h2.x; s1 += p.y * h2.y;
    p = __half22float2(*(const __half2*)&u.w); s0 += p.x * h3.x; s1 += p.y * h3.y;
    return s0 + s1;
}

__global__ void __launch_bounds__(NTHREADS, 1)
decoder_persistent_kernel(const float* __restrict__ start,
                          const float* __restrict__ enc,
                          const float* __restrict__ W_ih,
                          const float* __restrict__ W_hh,
                          const float* __restrict__ b_ih,
                          const float* __restrict__ b_hh,
                          const float* __restrict__ W_out,
                          const float* __restrict__ b_out,
                          const int*   __restrict__ maxlen_ptr,
                          float* __restrict__ out)
{
    extern __shared__ char smem_dyn[];
    __half* h_sh  = (__half*)smem_dyn;                       // 8 KB fp16 h
    __half* pin_w = (__half*)(smem_dyn + SMEM_H_BYTES);      // 216 KB pinned W
    float*  part  = (float*)(smem_dyn + SMEM_PART_OFF);      // [N_STREAM][3]

    const int lane   = threadIdx.x & 31;
    const int warp   = threadIdx.x >> 5;
    const int gwarp  = blockIdx.x * WARPS_PER_BLOCK + warp;
    const int gwarps = gridDim.x * WARPS_PER_BLOCK;
    const int gtid    = blockIdx.x * NTHREADS + threadIdx.x;
    const int gthreads = gridDim.x * NTHREADS;
    const int T = maxlen_ptr ? *maxlen_ptr : 2048;

    // ---- convert W_hh, W_out to fp16 scratch (every launch; deterministic) ----
    {
        const size_t total = (size_t)3 * HDIM * HDIM;
        for (size_t idx = (size_t)gtid * 4; idx < total; idx += (size_t)gthreads * 4) {
            float4 v = *(const float4*)(W_hh + idx);
            __half2* dst = (__half2*)(g_whh_h + idx);
            dst[0] = __floats2half2_rn(v.x, v.y);
            dst[1] = __floats2half2_rn(v.z, v.w);
        }
        const size_t ototal = (size_t)OROWS * HDIM;
        for (size_t idx = (size_t)gtid * 4; idx < ototal; idx += (size_t)gthreads * 4) {
            float4 v = *(const float4*)(W_out + idx);
            __half2* dst = (__half2*)(g_wout_h + idx);
            dst[0] = __floats2half2_rn(v.x, v.y);
            dst[1] = __floats2half2_rn(v.z, v.w);
        }
    }

    // ---- fill pinned smem weights for warps 0..PINNED_WARPS-1 (once) ----
    for (int idx = threadIdx.x * 4; idx < PIN_HALVES; idx += NTHREADS * 4) {
        int w   = idx / (3 * HDIM);
        int rem = idx - w * 3 * HDIM;
        int g   = rem / HDIM;
        int col = rem - g * HDIM;
        int row = blockIdx.x * WARPS_PER_BLOCK + w;
        if (row < HDIM) {
            float4 v = *(const float4*)(W_hh + ((size_t)(g * HDIM + row)) * HDIM + col);
            __half2* dst = (__half2*)(pin_w + idx);
            dst[0] = __floats2half2_rn(v.x, v.y);
            dst[1] = __floats2half2_rn(v.z, v.w);
        }
    }

    // ---- init: h0 = encoder_hidden (fp32 + fp16 copies) ----
    for (int idx = gtid; idx < HDIM; idx += gthreads) {
        float v = enc[idx];
        g_h[0][idx] = v;
        g_h16[0][idx] = __float2half_rn(v);
    }

    // ---- gx = W_ih @ relu(start) + b_ih (once per launch, fp32) ----
    for (int r = gwarp; r < 3 * HDIM; r += gwarps) {
        const float* wr = W_ih + (size_t)r * IN_DIM;
        float acc = 0.f;
        for (int k = lane; k < IN_DIM; k += 32) {
            float x = start[k];
            x = x > 0.f ? x : 0.f;
            acc += wr[k] * x;
        }
        acc = warp_sum(acc);
        if (lane == 0) g_gx[r] = acc + b_ih[r];
    }
    grid_sync();

    // Stage-B rows on streaming warps 9..11 (they run only 12 Stage-A iters)
    int brow = -1;
    if (warp >= PINNED_WARPS && warp < PINNED_WARPS + 3) {
        int pid = blockIdx.x * 3 + (warp - PINNED_WARPS);
        if (pid < OROWS) brow = pid;
    }

    const int myrow = (gwarp < HDIM) ? gwarp : -1;

    // hoist per-row constants out of the time loop
    float c_br = 0.f, c_bz = 0.f, c_bn = 0.f, c_gr = 0.f, c_gz = 0.f, c_gn = 0.f;
    if (myrow >= 0) {
        c_br = b_hh[myrow];
        c_bz = b_hh[myrow + HDIM];
        c_bn = b_hh[myrow + 2 * HDIM];
        c_gr = g_gx[myrow];
        c_gz = g_gx[myrow + HDIM];
        c_gn = g_gx[myrow + 2 * HDIM];
    }
    const float c_bo = (brow >= 0) ? b_out[brow] : 0.f;

    const bool pinned = (warp < PINNED_WARPS);
    // owners of helped rows (9..26) do 3 groups; warp 27 does 4 (unhelped)
    const int ngroups = (warp == WARPS_PER_BLOCK - 1) ? 4 : 3;

    // helper row targets for pinned warps (local rows 9..26)
    const int help_lr0 = PINNED_WARPS + 2 * warp;
    const int help_lr1 = PINNED_WARPS + 2 * warp + 1;

    const __half2 z2 = __float2half2_rn(0.f);

    // one group (4 iterations) of the flat-HFMA2 triple dot, group index g
    auto dot_group = [&](const uint4* __restrict__ w0, const uint4* __restrict__ w1,
                         const uint4* __restrict__ w2, const uint4* __restrict__ hh,
                         int g, float& a0, float& a1, float& a2) {
        __half2 A0 = z2, B0 = z2, A1 = z2, B1 = z2, A2 = z2, B2 = z2;
#pragma unroll
        for (int j = 0; j < 4; j++) {
            int k = lane + (g * 4 + j) * 32;
            uint4 u0 = w0[k];
            uint4 u1 = w1[k];
            uint4 u2 = w2[k];
            uint4 hu = hh[k];
            __half2 hx = *(const __half2*)&hu.x;
            __half2 hy = *(const __half2*)&hu.y;
            __half2 hz = *(const __half2*)&hu.z;
            __half2 hw = *(const __half2*)&hu.w;
            A0 = __hfma2(*(const __half2*)&u0.x, hx, A0);
            B0 = __hfma2(*(const __half2*)&u0.y, hy, B0);
            A0 = __hfma2(*(const __half2*)&u0.z, hz, A0);
            B0 = __hfma2(*(const __half2*)&u0.w, hw, B0);
            A1 = __hfma2(*(const __half2*)&u1.x, hx, A1);
            B1 = __hfma2(*(const __half2*)&u1.y, hy, B1);
            A1 = __hfma2(*(const __half2*)&u1.z, hz, A1);
            B1 = __hfma2(*(const __half2*)&u1.w, hw, B1);
            A2 = __hfma2(*(const __half2*)&u2.x, hx, A2);
            B2 = __hfma2(*(const __half2*)&u2.y, hy, B2);
            A2 = __hfma2(*(const __half2*)&u2.z, hz, A2);
            B2 = __hfma2(*(const __half2*)&u2.w, hw, B2);
        }
        float2 f0 = __half22float2(__hadd2(A0, B0));
        float2 f1 = __half22float2(__hadd2(A1, B1));
        float2 f2 = __half22float2(__hadd2(A2, B2));
        a0 += f0.x + f0.y;
        a1 += f1.x + f1.y;
        a2 += f2.x + f2.y;
    };

    // ---- main recurrence ----
    for (int t = 0; t < T; t++) {
        const float*  __restrict__ hc   = g_h[t & 1];
        float*        __restrict__ hn   = g_h[(t + 1) & 1];
        const __half* __restrict__ hc16 = g_h16[t & 1];
        __half*       __restrict__ hn16 = g_h16[(t + 1) & 1];
        const uint4* hh = (const uint4*)h_sh;

        // exact fp32 h_old for the recurrent z*h term (issued early; L2 hit)
        float h_old = (myrow >= 0) ? hc[myrow] : 0.f;

        // stage fp16 h_cur into shared memory (raw 8 KB copy)
        {
            const uint4* src = (const uint4*)hc16;
            uint4* dst = (uint4*)h_sh;
            for (int idx = threadIdx.x; idx < HDIM / 8; idx += NTHREADS)
                dst[idx] = src[idx];
        }
        __syncthreads();

        if (pinned) {
            // (1) own pinned row: full 16 LDS iterations + gates (no helpers)
            if (myrow >= 0) {
                const __half* sw = pin_w + (size_t)warp * 3 * HDIM;
                float a0 = 0.f, a1 = 0.f, a2 = 0.f;
#pragma unroll
                for (int g = 0; g < 4; g++)
                    dot_group((const uint4*)sw, (const uint4*)(sw + HDIM),
                              (const uint4*)(sw + 2 * HDIM), hh, g, a0, a1, a2);
                a0 = warp_sum(a0);
                a1 = warp_sum(a1);
                a2 = warp_sum(a2);
                float r = fast_sigmoid(c_gr + a0 + c_br);
                float z = fast_sigmoid(c_gz + a1 + c_bz);
                float n = fast_tanh(c_gn + r * (a2 + c_bn));
                if (lane == 0) {
                    float hv = (1.f - z) * n + z * h_old;
                    hn[myrow] = hv;
                    hn16[myrow] = __float2half_rn(hv);
                }
            }
            // (2) helper: group g=3 of two streaming rows (global weights)
#pragma unroll
            for (int hrep = 0; hrep < 2; hrep++) {
                int lr = (hrep == 0) ? help_lr0 : help_lr1;
                int grow = blockIdx.x * WARPS_PER_BLOCK + lr;
                if (lr < WARPS_PER_BLOCK && grow < HDIM) {
                    const uint4* w0 = (const uint4*)(g_whh_h + (size_t)grow * HDIM);
                    const uint4* w1 = (const uint4*)(g_whh_h + ((size_t)grow + HDIM) * HDIM);
                    const uint4* w2 = (const uint4*)(g_whh_h + ((size_t)grow + 2 * HDIM) * HDIM);
                    float p0 = 0.f, p1 = 0.f, p2 = 0.f;
                    dot_group(w0, w1, w2, hh, 3, p0, p1, p2);
                    p0 = warp_sum(p0);
                    p1 = warp_sum(p1);
                    p2 = warp_sum(p2);
                    if (lane == 0) {
                        float* pp = part + (lr - PINNED_WARPS) * 3;
                        pp[0] = p0; pp[1] = p1; pp[2] = p2;
                    }
                }
            }
        } else if (myrow >= 0) {
            // streaming owner: groups 0..ngroups-1 (LDG)
            const uint4* w0 = (const uint4*)(g_whh_h + (size_t)myrow * HDIM);
            const uint4* w1 = (const uint4*)(g_whh_h + ((size_t)myrow + HDIM) * HDIM);
            const uint4* w2 = (const uint4*)(g_whh_h + ((size_t)myrow + 2 * HDIM) * HDIM);
            float a0 = 0.f, a1 = 0.f, a2 = 0.f;
#pragma unroll
            for (int g = 0; g < 3; g++)
                dot_group(w0, w1, w2, hh, g, a0, a1, a2);
            if (ngroups == 4)
                dot_group(w0, w1, w2, hh, 3, a0, a1, a2);
            a0 = warp_sum(a0);
            a1 = warp_sum(a1);
            a2 = warp_sum(a2);
            // stash pre-combine sums in registers; combine after mid-sync
            // (use c_* later). Save into locals via pair trick:
            // fallthrough below via shared control — store in thread-locals:
            // (kept live across the __syncthreads)
            // gates happen after mid-sync
            // store partial accumulators:
            // reuse variables by writing to part? No — keep in regs:
            // handled below via a second branch using saved a0,a1,a2.
            // To keep them live, write them into per-thread storage:
            // simplest: do the combine here only for warp 27 (no helper),
            // others after sync.
            if (ngroups == 4) {
                float r = fast_sigmoid(c_gr + a0 + c_br);
                float z = fast_sigmoid(c_gz + a1 + c_bz);
                float n = fast_tanh(c_gn + r * (a2 + c_bn));
                if (lane == 0) {
                    float hv = (1.f - z) * n + z * h_old;
                    hn[myrow] = hv;
                    hn16[myrow] = __float2half_rn(hv);
                }
            } else if (lane == 0) {
                // temporarily park own sums in the partial slot (add helper later)
                // helper writes BEFORE midsync; owner must not race: owner adds
                // its own sums into registers and reads helper slot after sync.
                // Keep a0,a1,a2 in registers (live across sync) — nothing to do.
            }
            // Stage B (deferred, step t-1) for warps 9..11 — before mid-sync
            if (t > 0 && brow >= 0) {
                const uint4* wr = (const uint4*)(g_wout_h + (size_t)brow * HDIM);
                float acc = 0.f;
#pragma unroll
                for (int g = 0; g < 4; g++) {
                    __half2 A = z2, B = z2;
#pragma unroll
                    for (int j = 0; j < 4; j++) {
                        int k = lane + (g * 4 + j) * 32;
                        uint4 u = wr[k];
                        uint4 hu = hh[k];
                        A = __hfma2(*(const __half2*)&u.x, *(const __half2*)&hu.x, A);
                        B = __hfma2(*(const __half2*)&u.y, *(const __half2*)&hu.y, B);
                        A = __hfma2(*(const __half2*)&u.z, *(const __half2*)&hu.z, A);
                        B = __hfma2(*(const __half2*)&u.w, *(const __half2*)&hu.w, B);
                    }
                    float2 f = __half22float2(__hadd2(A, B));
                    acc += f.x + f.y;
                }
                acc = warp_sum(acc);
                if (lane == 0) {
                    float o = acc + c_bo;
                    int tt = t - 1;
                    if (brow < NOUT)
                        out[(size_t)tt * NOUT + brow] = fast_tanh(o);
                    else
                        out[(size_t)T * NOUT + tt] = fast_sigmoid(o);
                }
            }
            __syncthreads();   // helpers' partials visible
            if (ngroups == 3) {
                float* pp = part + (warp - PINNED_WARPS) * 3;
                float r = fast_sigmoid(c_gr + (a0 + pp[0]) + c_br);
                float z = fast_sigmoid(c_gz + (a1 + pp[1]) + c_bz);
                float n = fast_tanh(c_gn + r * ((a2 + pp[2]) + c_bn));
                if (lane == 0) {
                    float hv = (1.f - z) * n + z * h_old;
                    hn[myrow] = hv;
                    hn16[myrow] = __float2half_rn(hv);
                }
            }
            grid_sync();
            continue;   // owners took the sync path here
        }
        // pinned warps + inactive warps reach here: match the owners' syncs
        __syncthreads();
        grid_sync();
    }

    // ---- final Stage B for step T-1 (fp32 h from global) ----
    if (brow >= 0) {
        const float* hf = g_h[T & 1];
        const uint4* wr = (const uint4*)(g_wout_h + (size_t)brow * HDIM);
        float acc = 0.f;
#pragma unroll 4
        for (int k = lane; k < HDIM / 8; k += 32) {
            uint4 u = wr[k];
            const float4* hp = (const float4*)(hf + k * 8);
            float4 ha = hp[0], hb = hp[1];
            acc += dot8f(u, make_float2(ha.x, ha.y), make_float2(ha.z, ha.w),
                            make_float2(hb.x, hb.y), make_float2(hb.z, hb.w));
        }
        acc = warp_sum(acc);
        if (lane == 0) {
            float o = acc + c_bo;
            int tt = T - 1;
            if (brow < NOUT)
                out[(size_t)tt * NOUT + brow] = fast_tanh(o);
            else
                out[(size_t)T * NOUT + tt] = fast_sigmoid(o);
        }
    }
}

extern "C" void kernel_launch(void* const* d_in, const int* in_sizes, int n_in,
                              void* d_out, int out_size) {
    (void)in_sizes; (void)out_size;

    int dev = 0;
    cudaGetDevice(&dev);
    int sm = 148;
    cudaDeviceGetAttribute(&sm, cudaDevAttrMultiProcessorCount, dev);
    if (sm < 1) sm = 148;
    if (sm > 512) sm = 512;

    cudaFuncSetAttribute(decoder_persistent_kernel,
                         cudaFuncAttributeMaxDynamicSharedMemorySize, SMEM_TOTAL);

    const float* start = (const float*)d_in[0];
    const float* enc   = (const float*)d_in[1];
    const float* W_ih  = (const float*)d_in[2];
    const float* W_hh  = (const float*)d_in[3];
    const float* b_ih  = (const float*)d_in[4];
    const float* b_hh  = (const float*)d_in[5];
    const float* W_out = (const float*)d_in[6];
    const float* b_out = (const float*)d_in[7];
    const int* maxlen  = (n_in > 8) ? (const int*)d_in[8] : nullptr;

    decoder_persistent_kernel<<<sm, NTHREADS, SMEM_TOTAL>>>(
        start, enc, W_ih, W_hh, b_ih, b_hh, W_out, b_out, maxlen, (float*)d_out);
}

// round 15
// speedup vs baseline: 1.8533x; 1.8533x over previous
#include <cuda_runtime.h>
#include <cuda_fp16.h>
#include <cstdint>

// GRU decoder, H=4096, T=2048. Persistent single kernel + software grid barrier.
// R2: fp16 weight scratch -> L2-resident.   R6: batched loads + fast gates.
// R9: 9 warps' weights pinned in SMEM -> DRAM ~0%.
// R10: fp16 h in smem.  R12: Stage B on low-load warps.
// R13: flat HFMA2 group-flushed dots + fp16 h global buffer.       [14.96 ms]
// R14 lesson: helper-warp balancing added a sync + divergence -> 2x regression,
//             reverted. R13 loop shape is the established optimum.
// R15: R13 + pre-sync weight prefetch: streaming warps issue their first
//      chunk's 3 LDG.128s BEFORE the staging __syncthreads, hiding one L2
//      round-trip (~250 cyc) per step behind the staging copy.

#define HDIM 4096
#define IN_DIM 400
#define OROWS 401
#define NOUT 400
#define WARPS_PER_BLOCK 28
#define NTHREADS (WARPS_PER_BLOCK * 32)
#define PINNED_WARPS 9

#define SMEM_H_BYTES (HDIM * 2)                                  // 8192 (fp16 h)
#define PIN_HALVES (PINNED_WARPS * 3 * HDIM)                     // 110592 halves
#define SMEM_TOTAL (SMEM_H_BYTES + PIN_HALVES * 2)               // 229376 B

__device__ __half g_whh_h[(size_t)3 * HDIM * HDIM];   // 100.7 MB fp16 W_hh
__device__ __half g_wout_h[(size_t)OROWS * HDIM];     // 3.3 MB fp16 W_out
__device__ float  g_h[2][HDIM];                       // fp32 hidden (recurrence)
__device__ __half g_h16[2][HDIM];                     // fp16 hidden (dot inputs)
__device__ float  g_gx[3 * HDIM];                     // W_ih @ relu(x) + b_ih
__device__ unsigned g_cnt;
__device__ unsigned g_gen;

__device__ __forceinline__ float warp_sum(float v) {
#pragma unroll
    for (int o = 16; o; o >>= 1) v += __shfl_xor_sync(0xffffffffu, v, o);
    return v;
}

// Sense-reversing grid barrier; all blocks co-resident (grid == #SMs, 1 blk/SM).
__device__ __forceinline__ void grid_sync() {
    __syncthreads();
    if (threadIdx.x == 0) {
        __threadfence();
        unsigned gen = *(volatile unsigned*)&g_gen;
        unsigned nblk = gridDim.x;
        if (atomicAdd(&g_cnt, 1u) == nblk - 1u) {
            atomicExch(&g_cnt, 0u);
            __threadfence();
            atomicAdd(&g_gen, 1u);
        } else {
            while (*(volatile unsigned*)&g_gen == gen) { __nanosleep(32); }
        }
        __threadfence();
    }
    __syncthreads();
}

__device__ __forceinline__ float fast_sigmoid(float x) {
    float e;
    asm("ex2.approx.f32 %0, %1;" : "=f"(e) : "f"(-1.4426950408889634f * x));
    float r;
    asm("rcp.approx.f32 %0, %1;" : "=f"(r) : "f"(1.0f + e));
    return r;
}
__device__ __forceinline__ float fast_tanh(float x) {
    float r;
    asm("tanh.approx.f32 %0, %1;" : "=f"(r) : "f"(x));
    return r;
}

// fp32-h variant for the final Stage B (h from global, fp32)
__device__ __forceinline__ float dot8f(uint4 u, float2 h0, float2 h1,
                                       float2 h2, float2 h3) {
    float2 p; float s0 = 0.f, s1 = 0.f;
    p = __half22float2(*(const __half2*)&u.x); s0 += p.x * h0.x; s1 += p.y * h0.y;
    p = __half22float2(*(const __half2*)&u.y); s0 += p.x * h1.x; s1 += p.y * h1.y;
    p = __half22float2(*(const __half2*)&u.z); s0 += p.x * h2.x; s1 += p.y * h2.y;
    p = __half22float2(*(const __half2*)&u.w); s0 += p.x * h3.x; s1 += p.y * h3.y;
    return s0 + s1;
}

__global__ void __launch_bounds__(NTHREADS, 1)
decoder_persistent_kernel(const float* __restrict__ start,
                          const float* __restrict__ enc,
                          const float* __restrict__ W_ih,
                          const float* __restrict__ W_hh,
                          const float* __restrict__ b_ih,
                          const float* __restrict__ b_hh,
                          const float* __restrict__ W_out,
                          const float* __restrict__ b_out,
                          const int*   __restrict__ maxlen_ptr,
                          float* __restrict__ out)
{
    extern __shared__ char smem_dyn[];
    __half* h_sh  = (__half*)smem_dyn;                      // 8 KB fp16 h
    __half* pin_w = (__half*)(smem_dyn + SMEM_H_BYTES);     // 216 KB pinned W

    const int lane   = threadIdx.x & 31;
    const int warp   = threadIdx.x >> 5;
    const int gwarp  = blockIdx.x * WARPS_PER_BLOCK + warp;
    const int gwarps = gridDim.x * WARPS_PER_BLOCK;
    const int gtid    = blockIdx.x * NTHREADS + threadIdx.x;
    const int gthreads = gridDim.x * NTHREADS;
    const int T = maxlen_ptr ? *maxlen_ptr : 2048;

    // ---- convert W_hh, W_out to fp16 scratch (every launch; deterministic) ----
    {
        const size_t total = (size_t)3 * HDIM * HDIM;
        for (size_t idx = (size_t)gtid * 4; idx < total; idx += (size_t)gthreads * 4) {
            float4 v = *(const float4*)(W_hh + idx);
            __half2* dst = (__half2*)(g_whh_h + idx);
            dst[0] = __floats2half2_rn(v.x, v.y);
            dst[1] = __floats2half2_rn(v.z, v.w);
        }
        const size_t ototal = (size_t)OROWS * HDIM;
        for (size_t idx = (size_t)gtid * 4; idx < ototal; idx += (size_t)gthreads * 4) {
            float4 v = *(const float4*)(W_out + idx);
            __half2* dst = (__half2*)(g_wout_h + idx);
            dst[0] = __floats2half2_rn(v.x, v.y);
            dst[1] = __floats2half2_rn(v.z, v.w);
        }
    }

    // ---- fill pinned smem weights for warps 0..PINNED_WARPS-1 (once) ----
    for (int idx = threadIdx.x * 4; idx < PIN_HALVES; idx += NTHREADS * 4) {
        int w   = idx / (3 * HDIM);
        int rem = idx - w * 3 * HDIM;
        int g   = rem / HDIM;
        int col = rem - g * HDIM;
        int row = blockIdx.x * WARPS_PER_BLOCK + w;
        if (row < HDIM) {
            float4 v = *(const float4*)(W_hh + ((size_t)(g * HDIM + row)) * HDIM + col);
            __half2* dst = (__half2*)(pin_w + idx);
            dst[0] = __floats2half2_rn(v.x, v.y);
            dst[1] = __floats2half2_rn(v.z, v.w);
        }
    }

    // ---- init: h0 = encoder_hidden (fp32 + fp16 copies) ----
    for (int idx = gtid; idx < HDIM; idx += gthreads) {
        float v = enc[idx];
        g_h[0][idx] = v;
        g_h16[0][idx] = __float2half_rn(v);
    }

    // ---- gx = W_ih @ relu(start) + b_ih (once per launch, fp32) ----
    for (int r = gwarp; r < 3 * HDIM; r += gwarps) {
        const float* wr = W_ih + (size_t)r * IN_DIM;
        float acc = 0.f;
        for (int k = lane; k < IN_DIM; k += 32) {
            float x = start[k];
            x = x > 0.f ? x : 0.f;
            acc += wr[k] * x;
        }
        acc = warp_sum(acc);
        if (lane == 0) g_gx[r] = acc + b_ih[r];
    }
    grid_sync();

    // Stage-B rows assigned to PINNED warps only (no LDG in their Stage A).
    int brow = -1;
    if (warp < PINNED_WARPS) {
        int pid = blockIdx.x * PINNED_WARPS + warp;
        if ((pid % 3) == 0 && (pid / 3) < OROWS) brow = pid / 3;
    }

    const int myrow = (gwarp < HDIM) ? gwarp : -1;

    // hoist per-row constants out of the time loop
    float c_br = 0.f, c_bz = 0.f, c_bn = 0.f, c_gr = 0.f, c_gz = 0.f, c_gn = 0.f;
    if (myrow >= 0) {
        c_br = b_hh[myrow];
        c_bz = b_hh[myrow + HDIM];
        c_bn = b_hh[myrow + 2 * HDIM];
        c_gr = g_gx[myrow];
        c_gz = g_gx[myrow + HDIM];
        c_gn = g_gx[myrow + 2 * HDIM];
    }
    const float c_bo = (brow >= 0) ? b_out[brow] : 0.f;

    const bool pinned = (warp < PINNED_WARPS);
    const bool streaming = (!pinned) && (myrow >= 0);

    // hoisted weight base pointers (constant per warp)
    const uint4* w0 = streaming ? (const uint4*)(g_whh_h + (size_t)myrow * HDIM)
                                : (const uint4*)(pin_w + (size_t)warp * 3 * HDIM);
    const uint4* w1 = streaming ? (const uint4*)(g_whh_h + ((size_t)myrow + HDIM) * HDIM)
                                : (const uint4*)(pin_w + (size_t)warp * 3 * HDIM + HDIM / 8);
    const uint4* w2 = streaming ? (const uint4*)(g_whh_h + ((size_t)myrow + 2 * HDIM) * HDIM)
                                : (const uint4*)(pin_w + (size_t)warp * 3 * HDIM + 2 * (HDIM / 8));
    // NOTE: pin_w pointer arithmetic above is in uint4 units via casts below.

    const __half* pin_base = pin_w + (size_t)warp * 3 * HDIM;

    const __half2 z2 = __float2half2_rn(0.f);

    // ---- main recurrence ----
    for (int t = 0; t < T; t++) {
        const float*  __restrict__ hc   = g_h[t & 1];
        float*        __restrict__ hn   = g_h[(t + 1) & 1];
        const __half* __restrict__ hc16 = g_h16[t & 1];
        __half*       __restrict__ hn16 = g_h16[(t + 1) & 1];
        const uint4* hh = (const uint4*)h_sh;

        // exact fp32 h_old for the recurrent z*h term (issued early; L2 hit)
        float h_old = (myrow >= 0) ? hc[myrow] : 0.f;

        // PRE-SYNC PREFETCH: streaming warps issue first chunk's weight loads
        // now; they complete during the staging copy + sync below.
        uint4 pf0, pf1, pf2;
        if (streaming) {
            pf0 = ((const uint4*)(g_whh_h + (size_t)myrow * HDIM))[lane];
            pf1 = ((const uint4*)(g_whh_h + ((size_t)myrow + HDIM) * HDIM))[lane];
            pf2 = ((const uint4*)(g_whh_h + ((size_t)myrow + 2 * HDIM) * HDIM))[lane];
        }

        // stage fp16 h_cur into shared memory (raw 8 KB copy, no cvt)
        {
            const uint4* src = (const uint4*)hc16;
            uint4* dst = (uint4*)h_sh;
            for (int idx = threadIdx.x; idx < HDIM / 8; idx += NTHREADS)
                dst[idx] = src[idx];
        }
        __syncthreads();

        // Stage A: one warp per output i (flat HFMA2, group-flushed)
        if (myrow >= 0) {
            const uint4* v0;
            const uint4* v1;
            const uint4* v2;
            if (pinned) {
                v0 = (const uint4*)pin_base;
                v1 = (const uint4*)(pin_base + HDIM);
                v2 = (const uint4*)(pin_base + 2 * HDIM);
            } else {
                v0 = (const uint4*)(g_whh_h + (size_t)myrow * HDIM);
                v1 = (const uint4*)(g_whh_h + ((size_t)myrow + HDIM) * HDIM);
                v2 = (const uint4*)(g_whh_h + ((size_t)myrow + 2 * HDIM) * HDIM);
            }
            float a0 = 0.f, a1 = 0.f, a2 = 0.f;
#pragma unroll
            for (int g = 0; g < 4; g++) {
                __half2 A0 = z2, B0 = z2, A1 = z2, B1 = z2, A2 = z2, B2 = z2;
#pragma unroll
                for (int j = 0; j < 4; j++) {
                    int k = lane + (g * 4 + j) * 32;
                    uint4 u0, u1, u2;
                    if (g == 0 && j == 0 && streaming) {
                        u0 = pf0; u1 = pf1; u2 = pf2;   // prefetched pre-sync
                    } else {
                        u0 = v0[k]; u1 = v1[k]; u2 = v2[k];
                    }
                    uint4 hu = hh[k];
                    __half2 hx = *(const __half2*)&hu.x;
                    __half2 hy = *(const __half2*)&hu.y;
                    __half2 hz = *(const __half2*)&hu.z;
                    __half2 hw = *(const __half2*)&hu.w;
                    A0 = __hfma2(*(const __half2*)&u0.x, hx, A0);
                    B0 = __hfma2(*(const __half2*)&u0.y, hy, B0);
                    A0 = __hfma2(*(const __half2*)&u0.z, hz, A0);
                    B0 = __hfma2(*(const __half2*)&u0.w, hw, B0);
                    A1 = __hfma2(*(const __half2*)&u1.x, hx, A1);
                    B1 = __hfma2(*(const __half2*)&u1.y, hy, B1);
                    A1 = __hfma2(*(const __half2*)&u1.z, hz, A1);
                    B1 = __hfma2(*(const __half2*)&u1.w, hw, B1);
                    A2 = __hfma2(*(const __half2*)&u2.x, hx, A2);
                    B2 = __hfma2(*(const __half2*)&u2.y, hy, B2);
                    A2 = __hfma2(*(const __half2*)&u2.z, hz, A2);
                    B2 = __hfma2(*(const __half2*)&u2.w, hw, B2);
                }
                float2 f0 = __half22float2(__hadd2(A0, B0));
                float2 f1 = __half22float2(__hadd2(A1, B1));
                float2 f2 = __half22float2(__hadd2(A2, B2));
                a0 += f0.x + f0.y;
                a1 += f1.x + f1.y;
                a2 += f2.x + f2.y;
            }
            a0 = warp_sum(a0);
            a1 = warp_sum(a1);
            a2 = warp_sum(a2);
            float r = fast_sigmoid(c_gr + a0 + c_br);
            float z = fast_sigmoid(c_gz + a1 + c_bz);
            float n = fast_tanh(c_gn + r * (a2 + c_bn));
            if (lane == 0) {
                float hv = (1.f - z) * n + z * h_old;
                hn[myrow] = hv;
                hn16[myrow] = __float2half_rn(hv);
            }
        }

        // Stage B (deferred, for step t-1): pinned warps only; h from h_sh.
        if (t > 0 && brow >= 0) {
            const uint4* wr = (const uint4*)(g_wout_h + (size_t)brow * HDIM);
            float acc = 0.f;
#pragma unroll
            for (int g = 0; g < 4; g++) {
                __half2 A = z2, B = z2;
#pragma unroll
                for (int j = 0; j < 4; j++) {
                    int k = lane + (g * 4 + j) * 32;
                    uint4 u = wr[k];
                    uint4 hu = hh[k];
                    A = __hfma2(*(const __half2*)&u.x, *(const __half2*)&hu.x, A);
                    B = __hfma2(*(const __half2*)&u.y, *(const __half2*)&hu.y, B);
                    A = __hfma2(*(const __half2*)&u.z, *(const __half2*)&hu.z, A);
                    B = __hfma2(*(const __half2*)&u.w, *(const __half2*)&hu.w, B);
                }
                float2 f = __half22float2(__hadd2(A, B));
                acc += f.x + f.y;
            }
            acc = warp_sum(acc);
            if (lane == 0) {
                float o = acc + c_bo;
                int tt = t - 1;
                if (brow < NOUT)
                    out[(size_t)tt * NOUT + brow] = fast_tanh(o);
                else
                    out[(size_t)T * NOUT + tt] = fast_sigmoid(o);
            }
        }

        grid_sync();   // h_new(t) globally visible
    }

    // ---- final Stage B for step T-1 (fp32 h from global) ----
    if (brow >= 0) {
        const float* hf = g_h[T & 1];
        const uint4* wr = (const uint4*)(g_wout_h + (size_t)brow * HDIM);
        float acc = 0.f;
#pragma unroll 4
        for (int k = lane; k < HDIM / 8; k += 32) {
            uint4 u = wr[k];
            const float4* hp = (const float4*)(hf + k * 8);
            float4 ha = hp[0], hb = hp[1];
            acc += dot8f(u, make_float2(ha.x, ha.y), make_float2(ha.z, ha.w),
                            make_float2(hb.x, hb.y), make_float2(hb.z, hb.w));
        }
        acc = warp_sum(acc);
        if (lane == 0) {
            float o = acc + c_bo;
            int tt = T - 1;
            if (brow < NOUT)
                out[(size_t)tt * NOUT + brow] = fast_tanh(o);
            else
                out[(size_t)T * NOUT + tt] = fast_sigmoid(o);
        }
    }
}

extern "C" void kernel_launch(void* const* d_in, const int* in_sizes, int n_in,
                              void* d_out, int out_size) {
    (void)in_sizes; (void)out_size;

    int dev = 0;
    cudaGetDevice(&dev);
    int sm = 148;
    cudaDeviceGetAttribute(&sm, cudaDevAttrMultiProcessorCount, dev);
    if (sm < 1) sm = 148;
    if (sm > 512) sm = 512;

    cudaFuncSetAttribute(decoder_persistent_kernel,
                         cudaFuncAttributeMaxDynamicSharedMemorySize, SMEM_TOTAL);

    const float* start = (const float*)d_in[0];
    const float* enc   = (const float*)d_in[1];
    const float* W_ih  = (const float*)d_in[2];
    const float* W_hh  = (const float*)d_in[3];
    const float* b_ih  = (const float*)d_in[4];
    const float* b_hh  = (const float*)d_in[5];
    const float* W_out = (const float*)d_in[6];
    const float* b_out = (const float*)d_in[7];
    const int* maxlen  = (n_in > 8) ? (const int*)d_in[8] : nullptr;

    decoder_persistent_kernel<<<sm, NTHREADS, SMEM_TOTAL>>>(
        start, enc, W_ih, W_hh, b_ih, b_hh, W_out, b_out, maxlen, (float*)d_out);
}

// round 16
// speedup vs baseline: 1.9994x; 1.0788x over previous
#include <cuda_runtime.h>
#include <cuda_fp16.h>
#include <cstdint>

// GRU decoder, H=4096, T=2048. Persistent single kernel + software grid barrier.
// R2: fp16 weight scratch -> L2-resident.   R6: batched loads + fast gates.
// R9: 9 warps' weights pinned in SMEM -> DRAM ~0%.
// R10: fp16 h in smem.  R12: Stage B on pinned warps.
// R13: flat HFMA2 group-flushed dots + fp16 h global buffer.       [14.96 ms]
// R14/R15 lessons: any control-flow or sync restructure of the R13 body
//   regresses. This round changes ONLY the weight memory layout:
// R16: interleaved per-row weight blocks. Row i owns 1536 contiguous uint4;
//      iteration it's three 512B stream-slices sit at it*96 + {0,32,64}.
//      -> one base register, immediate-offset LDGs, one sequential 24KB
//      stream per warp per step. Same values, same accumulation order.

#define HDIM 4096
#define IN_DIM 400
#define OROWS 401
#define NOUT 400
#define WARPS_PER_BLOCK 28
#define NTHREADS (WARPS_PER_BLOCK * 32)
#define PINNED_WARPS 9
#define ROW_U4 1536          // uint4 per interleaved row block (3*4096 halves)

#define SMEM_H_BYTES (HDIM * 2)                                  // 8192 (fp16 h)
#define PIN_HALVES (PINNED_WARPS * 3 * HDIM)                     // 110592 halves
#define SMEM_TOTAL (SMEM_H_BYTES + PIN_HALVES * 2)               // 229376 B

__device__ __half g_whh_h[(size_t)3 * HDIM * HDIM];   // 100.7 MB fp16 W_hh (interleaved)
__device__ __half g_wout_h[(size_t)OROWS * HDIM];     // 3.3 MB fp16 W_out
__device__ float  g_h[2][HDIM];                       // fp32 hidden (recurrence)
__device__ __half g_h16[2][HDIM];                     // fp16 hidden (dot inputs)
__device__ float  g_gx[3 * HDIM];                     // W_ih @ relu(x) + b_ih
__device__ unsigned g_cnt;
__device__ unsigned g_gen;

__device__ __forceinline__ float warp_sum(float v) {
#pragma unroll
    for (int o = 16; o; o >>= 1) v += __shfl_xor_sync(0xffffffffu, v, o);
    return v;
}

// Sense-reversing grid barrier; all blocks co-resident (grid == #SMs, 1 blk/SM).
__device__ __forceinline__ void grid_sync() {
    __syncthreads();
    if (threadIdx.x == 0) {
        __threadfence();
        unsigned gen = *(volatile unsigned*)&g_gen;
        unsigned nblk = gridDim.x;
        if (atomicAdd(&g_cnt, 1u) == nblk - 1u) {
            atomicExch(&g_cnt, 0u);
            __threadfence();
            atomicAdd(&g_gen, 1u);
        } else {
            while (*(volatile unsigned*)&g_gen == gen) { __nanosleep(32); }
        }
        __threadfence();
    }
    __syncthreads();
}

__device__ __forceinline__ float fast_sigmoid(float x) {
    float e;
    asm("ex2.approx.f32 %0, %1;" : "=f"(e) : "f"(-1.4426950408889634f * x));
    float r;
    asm("rcp.approx.f32 %0, %1;" : "=f"(r) : "f"(1.0f + e));
    return r;
}
__device__ __forceinline__ float fast_tanh(float x) {
    float r;
    asm("tanh.approx.f32 %0, %1;" : "=f"(r) : "f"(x));
    return r;
}

// fp32-h variant for the final Stage B (h from global, fp32)
__device__ __forceinline__ float dot8f(uint4 u, float2 h0, float2 h1,
                                       float2 h2, float2 h3) {
    float2 p; float s0 = 0.f, s1 = 0.f;
    p = __half22float2(*(const __half2*)&u.x); s0 += p.x * h0.x; s1 += p.y * h0.y;
    p = __half22float2(*(const __half2*)&u.y); s0 += p.x * h1.x; s1 += p.y * h1.y;
    p = __half22float2(*(const __half2*)&u.z); s0 += p.x * h2.x; s1 += p.y * h2.y;
    p = __half22float2(*(const __half2*)&u.w); s0 += p.x * h3.x; s1 += p.y * h3.y;
    return s0 + s1;
}

// pack 8 consecutive fp32 -> uint4 of 8 fp16
__device__ __forceinline__ uint4 pack8(const float* src) {
    float4 a = ((const float4*)src)[0];
    float4 b = ((const float4*)src)[1];
    uint4 o;
    *(__half2*)&o.x = __floats2half2_rn(a.x, a.y);
    *(__half2*)&o.y = __floats2half2_rn(a.z, a.w);
    *(__half2*)&o.z = __floats2half2_rn(b.x, b.y);
    *(__half2*)&o.w = __floats2half2_rn(b.z, b.w);
    return o;
}

__global__ void __launch_bounds__(NTHREADS, 1)
decoder_persistent_kernel(const float* __restrict__ start,
                          const float* __restrict__ enc,
                          const float* __restrict__ W_ih,
                          const float* __restrict__ W_hh,
                          const float* __restrict__ b_ih,
                          const float* __restrict__ b_hh,
                          const float* __restrict__ W_out,
                          const float* __restrict__ b_out,
                          const int*   __restrict__ maxlen_ptr,
                          float* __restrict__ out)
{
    extern __shared__ char smem_dyn[];
    __half* h_sh  = (__half*)smem_dyn;                      // 8 KB fp16 h
    __half* pin_w = (__half*)(smem_dyn + SMEM_H_BYTES);     // 216 KB pinned W

    const int lane   = threadIdx.x & 31;
    const int warp   = threadIdx.x >> 5;
    const int gwarp  = blockIdx.x * WARPS_PER_BLOCK + warp;
    const int gwarps = gridDim.x * WARPS_PER_BLOCK;
    const int gtid    = blockIdx.x * NTHREADS + threadIdx.x;
    const int gthreads = gridDim.x * NTHREADS;
    const int T = maxlen_ptr ? *maxlen_ptr : 2048;

    // ---- convert W_hh into INTERLEAVED fp16 scratch ----
    // dst uint4 index d: row = d/1536; rem: it = rem/96, s = (rem%96)/32,
    // ln = rem%32; source cols = (it*32+ln)*8 of fp32 row (s*HDIM + row).
    {
        const int total4 = HDIM * ROW_U4;                 // 6,291,456
        uint4* dst = (uint4*)g_whh_h;
        for (int d = gtid; d < total4; d += gthreads) {
            int row = d / ROW_U4;
            int rem = d - row * ROW_U4;
            int it  = rem / 96;
            int r2  = rem - it * 96;
            int s   = r2 >> 5;
            int ln  = r2 & 31;
            int col = (it * 32 + ln) * 8;
            dst[d] = pack8(W_hh + ((size_t)(s * HDIM + row)) * HDIM + col);
        }
        const size_t ototal = (size_t)OROWS * HDIM;
        for (size_t idx = (size_t)gtid * 8; idx < ototal; idx += (size_t)gthreads * 8)
            ((uint4*)(g_wout_h + idx))[0] = pack8(W_out + idx);
    }

    // ---- fill pinned smem weights (same interleaved layout) ----
    {
        uint4* pdst = (uint4*)pin_w;
        for (int idx = threadIdx.x; idx < PINNED_WARPS * ROW_U4; idx += NTHREADS) {
            int w   = idx / ROW_U4;
            int rem = idx - w * ROW_U4;
            int it  = rem / 96;
            int r2  = rem - it * 96;
            int s   = r2 >> 5;
            int ln  = r2 & 31;
            int row = blockIdx.x * WARPS_PER_BLOCK + w;
            if (row < HDIM) {
                int col = (it * 32 + ln) * 8;
                pdst[idx] = pack8(W_hh + ((size_t)(s * HDIM + row)) * HDIM + col);
            }
        }
    }

    // ---- init: h0 = encoder_hidden (fp32 + fp16 copies) ----
    for (int idx = gtid; idx < HDIM; idx += gthreads) {
        float v = enc[idx];
        g_h[0][idx] = v;
        g_h16[0][idx] = __float2half_rn(v);
    }

    // ---- gx = W_ih @ relu(start) + b_ih (once per launch, fp32) ----
    for (int r = gwarp; r < 3 * HDIM; r += gwarps) {
        const float* wr = W_ih + (size_t)r * IN_DIM;
        float acc = 0.f;
        for (int k = lane; k < IN_DIM; k += 32) {
            float x = start[k];
            x = x > 0.f ? x : 0.f;
            acc += wr[k] * x;
        }
        acc = warp_sum(acc);
        if (lane == 0) g_gx[r] = acc + b_ih[r];
    }
    grid_sync();

    // Stage-B rows assigned to PINNED warps only (no LDG in their Stage A).
    int brow = -1;
    if (warp < PINNED_WARPS) {
        int pid = blockIdx.x * PINNED_WARPS + warp;
        if ((pid % 3) == 0 && (pid / 3) < OROWS) brow = pid / 3;
    }

    const int myrow = (gwarp < HDIM) ? gwarp : -1;

    // hoist per-row constants out of the time loop
    float c_br = 0.f, c_bz = 0.f, c_bn = 0.f, c_gr = 0.f, c_gz = 0.f, c_gn = 0.f;
    if (myrow >= 0) {
        c_br = b_hh[myrow];
        c_bz = b_hh[myrow + HDIM];
        c_bn = b_hh[myrow + 2 * HDIM];
        c_gr = g_gx[myrow];
        c_gz = g_gx[myrow + HDIM];
        c_gn = g_gx[myrow + 2 * HDIM];
    }
    const float c_bo = (brow >= 0) ? b_out[brow] : 0.f;

    const bool pinned = (warp < PINNED_WARPS);

    // one weight base pointer per warp (interleaved layout, fixed all launch)
    const uint4* wbase = pinned
        ? (const uint4*)pin_w + (size_t)warp * ROW_U4
        : (const uint4*)g_whh_h + (size_t)(myrow < 0 ? 0 : myrow) * ROW_U4;

    const __half2 z2 = __float2half2_rn(0.f);

    // ---- main recurrence ----
    for (int t = 0; t < T; t++) {
        const float*  __restrict__ hc   = g_h[t & 1];
        float*        __restrict__ hn   = g_h[(t + 1) & 1];
        const __half* __restrict__ hc16 = g_h16[t & 1];
        __half*       __restrict__ hn16 = g_h16[(t + 1) & 1];
        const uint4* hh = (const uint4*)h_sh;

        // exact fp32 h_old for the recurrent z*h term (issued early; L2 hit)
        float h_old = (myrow >= 0) ? hc[myrow] : 0.f;

        // stage fp16 h_cur into shared memory (raw 8 KB copy, no cvt)
        {
            const uint4* src = (const uint4*)hc16;
            uint4* dst = (uint4*)h_sh;
            for (int idx = threadIdx.x; idx < HDIM / 8; idx += NTHREADS)
                dst[idx] = src[idx];
        }
        __syncthreads();

        // Stage A: one warp per output i (flat HFMA2, group-flushed).
        // Interleaved weights: iteration it reads base[it*96 + lane + {0,32,64}].
        if (myrow >= 0) {
            float a0 = 0.f, a1 = 0.f, a2 = 0.f;
#pragma unroll
            for (int g = 0; g < 4; g++) {
                __half2 A0 = z2, B0 = z2, A1 = z2, B1 = z2, A2 = z2, B2 = z2;
#pragma unroll
                for (int j = 0; j < 4; j++) {
                    int it = g * 4 + j;
                    int kb = it * 96 + lane;
                    uint4 u0 = wbase[kb];
                    uint4 u1 = wbase[kb + 32];
                    uint4 u2 = wbase[kb + 64];
                    uint4 hu = hh[it * 32 + lane];
                    __half2 hx = *(const __half2*)&hu.x;
                    __half2 hy = *(const __half2*)&hu.y;
                    __half2 hz = *(const __half2*)&hu.z;
                    __half2 hw = *(const __half2*)&hu.w;
                    A0 = __hfma2(*(const __half2*)&u0.x, hx, A0);
                    B0 = __hfma2(*(const __half2*)&u0.y, hy, B0);
                    A0 = __hfma2(*(const __half2*)&u0.z, hz, A0);
                    B0 = __hfma2(*(const __half2*)&u0.w, hw, B0);
                    A1 = __hfma2(*(const __half2*)&u1.x, hx, A1);
                    B1 = __hfma2(*(const __half2*)&u1.y, hy, B1);
                    A1 = __hfma2(*(const __half2*)&u1.z, hz, A1);
                    B1 = __hfma2(*(const __half2*)&u1.w, hw, B1);
                    A2 = __hfma2(*(const __half2*)&u2.x, hx, A2);
                    B2 = __hfma2(*(const __half2*)&u2.y, hy, B2);
                    A2 = __hfma2(*(const __half2*)&u2.z, hz, A2);
                    B2 = __hfma2(*(const __half2*)&u2.w, hw, B2);
                }
                float2 f0 = __half22float2(__hadd2(A0, B0));
                float2 f1 = __half22float2(__hadd2(A1, B1));
                float2 f2 = __half22float2(__hadd2(A2, B2));
                a0 += f0.x + f0.y;
                a1 += f1.x + f1.y;
                a2 += f2.x + f2.y;
            }
            a0 = warp_sum(a0);
            a1 = warp_sum(a1);
            a2 = warp_sum(a2);
            float r = fast_sigmoid(c_gr + a0 + c_br);
            float z = fast_sigmoid(c_gz + a1 + c_bz);
            float n = fast_tanh(c_gn + r * (a2 + c_bn));
            if (lane == 0) {
                float hv = (1.f - z) * n + z * h_old;
                hn[myrow] = hv;
                hn16[myrow] = __float2half_rn(hv);
            }
        }

        // Stage B (deferred, for step t-1): pinned warps only; h from h_sh.
        if (t > 0 && brow >= 0) {
            const uint4* wr = (const uint4*)(g_wout_h + (size_t)brow * HDIM);
            float acc = 0.f;
#pragma unroll
            for (int g = 0; g < 4; g++) {
                __half2 A = z2, B = z2;
#pragma unroll
                for (int j = 0; j < 4; j++) {
                    int k = lane + (g * 4 + j) * 32;
                    uint4 u = wr[k];
                    uint4 hu = hh[k];
                    A = __hfma2(*(const __half2*)&u.x, *(const __half2*)&hu.x, A);
                    B = __hfma2(*(const __half2*)&u.y, *(const __half2*)&hu.y, B);
                    A = __hfma2(*(const __half2*)&u.z, *(const __half2*)&hu.z, A);
                    B = __hfma2(*(const __half2*)&u.w, *(const __half2*)&hu.w, B);
                }
                float2 f = __half22float2(__hadd2(A, B));
                acc += f.x + f.y;
            }
            acc = warp_sum(acc);
            if (lane == 0) {
                float o = acc + c_bo;
                int tt = t - 1;
                if (brow < NOUT)
                    out[(size_t)tt * NOUT + brow] = fast_tanh(o);
                else
                    out[(size_t)T * NOUT + tt] = fast_sigmoid(o);
            }
        }

        grid_sync();   // h_new(t) globally visible
    }

    // ---- final Stage B for step T-1 (fp32 h from global) ----
    if (brow >= 0) {
        const float* hf = g_h[T & 1];
        const uint4* wr = (const uint4*)(g_wout_h + (size_t)brow * HDIM);
        float acc = 0.f;
#pragma unroll 4
        for (int k = lane; k < HDIM / 8; k += 32) {
            uint4 u = wr[k];
            const float4* hp = (const float4*)(hf + k * 8);
            float4 ha = hp[0], hb = hp[1];
            acc += dot8f(u, make_float2(ha.x, ha.y), make_float2(ha.z, ha.w),
                            make_float2(hb.x, hb.y), make_float2(hb.z, hb.w));
        }
        acc = warp_sum(acc);
        if (lane == 0) {
            float o = acc + c_bo;
            int tt = T - 1;
            if (brow < NOUT)
                out[(size_t)tt * NOUT + brow] = fast_tanh(o);
            else
                out[(size_t)T * NOUT + tt] = fast_sigmoid(o);
        }
    }
}

extern "C" void kernel_launch(void* const* d_in, const int* in_sizes, int n_in,
                              void* d_out, int out_size) {
    (void)in_sizes; (void)out_size;

    int dev = 0;
    cudaGetDevice(&dev);
    int sm = 148;
    cudaDeviceGetAttribute(&sm, cudaDevAttrMultiProcessorCount, dev);
    if (sm < 1) sm = 148;
    if (sm > 512) sm = 512;

    cudaFuncSetAttribute(decoder_persistent_kernel,
                         cudaFuncAttributeMaxDynamicSharedMemorySize, SMEM_TOTAL);

    const float* start = (const float*)d_in[0];
    const float* enc   = (const float*)d_in[1];
    const float* W_ih  = (const float*)d_in[2];
    const float* W_hh  = (const float*)d_in[3];
    const float* b_ih  = (const float*)d_in[4];
    const float* b_hh  = (const float*)d_in[5];
    const float* W_out = (const float*)d_in[6];
    const float* b_out = (const float*)d_in[7];
    const int* maxlen  = (n_in > 8) ? (const int*)d_in[8] : nullptr;

    decoder_persistent_kernel<<<sm, NTHREADS, SMEM_TOTAL>>>(
        start, enc, W_ih, W_hh, b_ih, b_hh, W_out, b_out, maxlen, (float*)d_out);
}